// round 1
// baseline (speedup 1.0000x reference)
#include <cuda_runtime.h>
#include <cstdint>

#define BB 2
#define CC 64
#define HWD 64
#define NVOX (HWD*HWD*HWD)   /* 262144 */

// ---------------- device scratch (static, no allocation) ----------------
__device__ float    g_s[BB][CC];
__device__ float    g_mh[BB][HWD];
__device__ float    g_mw[BB][HWD];
__device__ float    g_md[BB][HWD];
__device__ float    g_M[BB];
__device__ float    g_u[BB][CC];
__device__ float    g_c0[BB];
__device__ float    g_qh[BB][HWD];
__device__ float    g_qw[BB][HWD];
__device__ float    g_qd[BB][HWD];
__device__ unsigned g_maxkey[BB];
__device__ float    g_sumexp[BB];
__device__ float    g_logits[BB][NVOX];   // logits, then overwritten with exp(l-max)

// ---------------- helpers ----------------
__device__ __forceinline__ unsigned enc_key(float f) {
    unsigned u = __float_as_uint(f);
    return (u >> 31) ? ~u : (u | 0x80000000u);
}
__device__ __forceinline__ float dec_key(unsigned e) {
    return (e & 0x80000000u) ? __uint_as_float(e ^ 0x80000000u)
                             : __uint_as_float(~e);
}
__device__ __forceinline__ unsigned long long pack2(float lo, float hi) {
    unsigned long long r;
    asm("mov.b64 %0, {%1, %2};" : "=l"(r) : "f"(lo), "f"(hi));
    return r;
}
__device__ __forceinline__ void fma2(unsigned long long& d, unsigned long long a,
                                     unsigned long long b) {
    asm("fma.rn.f32x2 %0, %1, %2, %0;" : "+l"(d) : "l"(a), "l"(b));
}
__device__ __forceinline__ float2 unpack2(unsigned long long v) {
    float2 r;
    asm("mov.b64 {%0, %1}, %2;" : "=f"(r.x), "=f"(r.y) : "l"(v));
    return r;
}

// ---------------- kernel 0: zero scratch ----------------
__global__ void k_zero() {
    int t = threadIdx.x;
    if (t < CC)  { g_s[0][t] = 0.f; g_s[1][t] = 0.f; }
    if (t < HWD) {
        g_mh[0][t] = 0.f; g_mh[1][t] = 0.f;
        g_mw[0][t] = 0.f; g_mw[1][t] = 0.f;
        g_md[0][t] = 0.f; g_md[1][t] = 0.f;
    }
    if (t < BB) { g_maxkey[t] = 0u; g_sumexp[t] = 0.f; }
}

// ---------------- kernel 1: masked reductions ----------------
// s[b,c] = sum_n mask*x ; mh/mw/md = per-axis mask marginals
__global__ void __launch_bounds__(256) k_reduce(const float* __restrict__ x,
                                                const float* __restrict__ mask) {
    const int b   = blockIdx.y;
    const float* xb = x    + (size_t)b * CC * NVOX;
    const float* mb = mask + (size_t)b * NVOX;
    __shared__ float ss[CC];
    __shared__ float sh[HWD], sw[HWD], sd[HWD];
    const int tid = threadIdx.x;
    for (int i = tid; i < CC;  i += 256) ss[i] = 0.f;
    for (int i = tid; i < HWD; i += 256) { sh[i] = 0.f; sw[i] = 0.f; sd[i] = 0.f; }
    __syncthreads();

    float acc[CC];
    #pragma unroll
    for (int c = 0; c < CC; c++) acc[c] = 0.f;

    const int nPairs = NVOX / 2;
    for (int p = blockIdx.x * 256 + tid; p < nPairs; p += gridDim.x * 256) {
        const int n = 2 * p;
        const float2 m2 = ((const float2*)mb)[p];
        const int d = n & 63, w = (n >> 6) & 63, h = n >> 12;  // h,w warp-uniform
        float wsum = m2.x + m2.y;
        #pragma unroll
        for (int o = 16; o; o >>= 1) wsum += __shfl_xor_sync(0xffffffffu, wsum, o);
        if ((tid & 31) == 0) { atomicAdd(&sh[h], wsum); atomicAdd(&sw[w], wsum); }
        atomicAdd(&sd[d],     m2.x);
        atomicAdd(&sd[d + 1], m2.y);
        #pragma unroll
        for (int c = 0; c < CC; c++) {
            const float2 v = ((const float2*)(xb + (size_t)c * NVOX))[p];
            acc[c] += m2.x * v.x + m2.y * v.y;
        }
    }
    #pragma unroll
    for (int c = 0; c < CC; c++) {
        float v = acc[c];
        #pragma unroll
        for (int o = 16; o; o >>= 1) v += __shfl_xor_sync(0xffffffffu, v, o);
        if ((tid & 31) == 0) atomicAdd(&ss[c], v);
    }
    __syncthreads();
    for (int i = tid; i < CC;  i += 256) atomicAdd(&g_s[b][i], ss[i]);
    for (int i = tid; i < HWD; i += 256) {
        atomicAdd(&g_mh[b][i], sh[i]);
        atomicAdd(&g_mw[b][i], sw[i]);
        atomicAdd(&g_md[b][i], sd[i]);
    }
}

// ---------------- kernel 2: tiny prep ----------------
// q = (Wq s + sum(mask*pe)) / M + bq ; u = Wk^T q ; c0 = q.bk ; qh/qw/qd = q.tabs
__global__ void k_prep(const float* __restrict__ Wk, const float* __restrict__ bk,
                       const float* __restrict__ Wq, const float* __restrict__ bq,
                       const float* __restrict__ h_tab, const float* __restrict__ w_tab,
                       const float* __restrict__ d_tab) {
    const int b = blockIdx.x;
    const int t = threadIdx.x;      // 64 threads: t doubles as ck / c / h index
    __shared__ float qs[CC];
    __shared__ float Msh;
    if (t == 0) {
        float M = 0.f;
        for (int h = 0; h < HWD; h++) M += g_mh[b][h];
        Msh = M; g_M[b] = M;
    }
    __syncthreads();
    {   // q[t]
        float a = 0.f;
        for (int c = 0; c < CC;  c++) a += Wq[t * CC + c] * g_s[b][c];
        for (int h = 0; h < HWD; h++) a += g_mh[b][h] * h_tab[h * CC + t];
        for (int w = 0; w < HWD; w++) a += g_mw[b][w] * w_tab[w * CC + t];
        for (int d = 0; d < HWD; d++) a += g_md[b][d] * d_tab[d * CC + t];
        qs[t] = a / Msh + bq[t];
    }
    __syncthreads();
    {   // u[t] = sum_ck q[ck] Wk[ck][t]
        float a = 0.f;
        for (int ck = 0; ck < CC; ck++) a += qs[ck] * Wk[ck * CC + t];
        g_u[b][t] = a;
    }
    if (t == 0) {
        float a = 0.f;
        for (int ck = 0; ck < CC; ck++) a += qs[ck] * bk[ck];
        g_c0[b] = a;
    }
    {   // qh/qw/qd[t]
        float a1 = 0.f, a2 = 0.f, a3 = 0.f;
        for (int ck = 0; ck < CC; ck++) {
            const float q = qs[ck];
            a1 += q * h_tab[t * CC + ck];
            a2 += q * w_tab[t * CC + ck];
            a3 += q * d_tab[t * CC + ck];
        }
        g_qh[b][t] = a1; g_qw[b][t] = a2; g_qd[b][t] = a3;
    }
}

// ---------------- kernel 3: logits + global max ----------------
__global__ void __launch_bounds__(256) k_logits(const float* __restrict__ x) {
    const int b = blockIdx.y;
    __shared__ float us[CC];
    __shared__ unsigned smax;
    const int tid = threadIdx.x;
    if (tid < CC) us[tid] = g_u[b][tid];
    if (tid == 0) smax = 0u;
    __syncthreads();
    const float* xb = x + (size_t)b * CC * NVOX;
    const float  c0 = g_c0[b];
    const int p = blockIdx.x * 256 + tid;        // pair index, exact cover
    const int n = 2 * p;
    float l0 = c0, l1 = c0;
    #pragma unroll
    for (int c = 0; c < CC; c++) {
        const float2 v = ((const float2*)(xb + (size_t)c * NVOX))[p];
        const float u = us[c];
        l0 += u * v.x;
        l1 += u * v.y;
    }
    const int d = n & 63, w = (n >> 6) & 63, h = n >> 12;
    const float pw = g_qh[b][h] + g_qw[b][w];
    l0 = (l0 + pw + g_qd[b][d])     * 0.125f;
    l1 = (l1 + pw + g_qd[b][d + 1]) * 0.125f;
    ((float2*)&g_logits[b][0])[p] = make_float2(l0, l1);
    float mx = fmaxf(l0, l1);
    #pragma unroll
    for (int o = 16; o; o >>= 1) mx = fmaxf(mx, __shfl_xor_sync(0xffffffffu, mx, o));
    if ((tid & 31) == 0) atomicMax(&smax, enc_key(mx));
    __syncthreads();
    if (tid == 0) atomicMax(&g_maxkey[b], smax);
}

// ---------------- kernel 4: exp + sum ----------------
__global__ void __launch_bounds__(256) k_expsum() {
    const int b = blockIdx.y;
    const float mx = dec_key(g_maxkey[b]);
    const int i = blockIdx.x * 256 + threadIdx.x;
    float2* lp = (float2*)&g_logits[b][0];
    const float2 l = lp[i];
    const float p0 = expf(l.x - mx), p1 = expf(l.y - mx);
    lp[i] = make_float2(p0, p1);
    float s = p0 + p1;
    #pragma unroll
    for (int o = 16; o; o >>= 1) s += __shfl_xor_sync(0xffffffffu, s, o);
    __shared__ float ws[8];
    const int wid = threadIdx.x >> 5;
    if ((threadIdx.x & 31) == 0) ws[wid] = s;
    __syncthreads();
    if (threadIdx.x == 0) {
        float t = 0.f;
        #pragma unroll
        for (int j = 0; j < 8; j++) t += ws[j];
        atomicAdd(&g_sumexp[b], t);
    }
}

// ---------------- kernel 5: vals GEMM (f32x2-packed) + scaled epilogue ----------------
// out[b,co,n] = scale_n * (sum_c Wv[co,c] x[b,c,n] + bv[co]),  scale = M * p / sumexp
// Block tile: 64 co x 64 vox.  Thread tile: 4 co x 4 vox (8 f32x2 accumulators).
__global__ void __launch_bounds__(256) k_out(const float* __restrict__ x,
                                             const float* __restrict__ Wv,
                                             const float* __restrict__ bv,
                                             float* __restrict__ out) {
    const int b  = blockIdx.y;
    const int n0 = blockIdx.x * 64;
    __shared__ float Ws[64][64];   // Ws[co][k] = Wv[co][k]
    __shared__ float Xs[64][64];   // Xs[k][vox]
    __shared__ float sc[64];
    const int tid = threadIdx.x;
    const int tx  = tid & 15;      // vox group (4 voxels)
    const int ty  = tid >> 4;      // co  group (4 channels)

    const float* xb = x + (size_t)b * CC * NVOX;
    // load Wv and x-tile as float4 (coalesced, conflict-free shared stores)
    for (int idx = tid; idx < 1024; idx += 256) {
        const int r = idx >> 4, c4 = idx & 15;
        *(float4*)&Ws[r][c4 * 4] = *(const float4*)&Wv[r * 64 + c4 * 4];
        *(float4*)&Xs[r][c4 * 4] = *(const float4*)&xb[(size_t)r * NVOX + n0 + c4 * 4];
    }
    if (tid < 64) {
        const float Mb  = g_M[b];
        const float inv = 1.f / g_sumexp[b];
        sc[tid] = Mb * inv * g_logits[b][n0 + tid];
    }
    __syncthreads();

    unsigned long long acc[4][2];
    #pragma unroll
    for (int i = 0; i < 4; i++) { acc[i][0] = 0ull; acc[i][1] = 0ull; }

    #pragma unroll 4
    for (int k0 = 0; k0 < 64; k0 += 4) {
        float4 wrow[4];
        #pragma unroll
        for (int i = 0; i < 4; i++) wrow[i] = *(const float4*)&Ws[ty * 4 + i][k0];
        #pragma unroll
        for (int kk = 0; kk < 4; kk++) {
            const float4 xv = *(const float4*)&Xs[k0 + kk][tx * 4];
            const unsigned long long xp0 = pack2(xv.x, xv.y);
            const unsigned long long xp1 = pack2(xv.z, xv.w);
            #pragma unroll
            for (int i = 0; i < 4; i++) {
                const float w = (kk == 0) ? wrow[i].x : (kk == 1) ? wrow[i].y
                              : (kk == 2) ? wrow[i].z : wrow[i].w;
                const unsigned long long wp = pack2(w, w);
                fma2(acc[i][0], wp, xp0);
                fma2(acc[i][1], wp, xp1);
            }
        }
    }

    const float s0 = sc[tx * 4 + 0], s1 = sc[tx * 4 + 1];
    const float s2 = sc[tx * 4 + 2], s3 = sc[tx * 4 + 3];
    #pragma unroll
    for (int i = 0; i < 4; i++) {
        const int co = ty * 4 + i;
        const float bvv = bv[co];
        const float2 a0 = unpack2(acc[i][0]);
        const float2 a1 = unpack2(acc[i][1]);
        float4 r;
        r.x = (a0.x + bvv) * s0;
        r.y = (a0.y + bvv) * s1;
        r.z = (a1.x + bvv) * s2;
        r.w = (a1.y + bvv) * s3;
        *(float4*)&out[((size_t)(b * 64 + co)) * NVOX + n0 + tx * 4] = r;
    }
}

// ---------------- host launcher ----------------
extern "C" void kernel_launch(void* const* d_in, const int* in_sizes, int n_in,
                              void* d_out, int out_size) {
    const float* x     = (const float*)d_in[0];
    const float* mask  = (const float*)d_in[1];
    const float* Wk    = (const float*)d_in[2];
    const float* bk    = (const float*)d_in[3];
    const float* Wv    = (const float*)d_in[4];
    const float* bv    = (const float*)d_in[5];
    const float* Wq    = (const float*)d_in[6];
    const float* bq    = (const float*)d_in[7];
    const float* h_tab = (const float*)d_in[8];
    const float* w_tab = (const float*)d_in[9];
    const float* d_tab = (const float*)d_in[10];
    float* out = (float*)d_out;

    k_zero  <<<1, 128>>>();
    k_reduce<<<dim3(256, BB), 256>>>(x, mask);
    k_prep  <<<BB, 64>>>(Wk, bk, Wq, bq, h_tab, w_tab, d_tab);
    k_logits<<<dim3(NVOX / 512, BB), 256>>>(x);
    k_expsum<<<dim3(NVOX / 512, BB), 256>>>();
    k_out   <<<dim3(NVOX / 64, BB), 256>>>(x, Wv, bv, out);

    // output tuple tail: mask passthrough
    cudaMemcpyAsync(out + (size_t)BB * CC * NVOX, mask,
                    (size_t)BB * NVOX * sizeof(float),
                    cudaMemcpyDeviceToDevice, 0);
}

// round 3
// speedup vs baseline: 1.1533x; 1.1533x over previous
#include <cuda_runtime.h>
#include <cuda_bf16.h>
#include <cstdint>

#define BB 2
#define CC 64
#define HWD 64
#define NVOX (HWD*HWD*HWD)   /* 262144 */
#define TILE_V 256

// ---------------- device scratch (static, no allocation) ----------------
__device__ float    g_s[BB][CC];
__device__ float    g_mh[BB][HWD];
__device__ float    g_mw[BB][HWD];
__device__ float    g_md[BB][HWD];
__device__ float    g_M[BB];
__device__ float    g_u[BB][CC];
__device__ float    g_c0[BB];
__device__ float    g_qh[BB][HWD];
__device__ float    g_qw[BB][HWD];
__device__ float    g_qd[BB][HWD];
__device__ unsigned g_maxkey[BB];
__device__ float    g_sumexp[BB];
__device__ float    g_logits[BB][NVOX];           // logits, then exp(l-max)
__device__ unsigned short g_Wh[CC * CC];          // Wv bf16-hi, swizzled [n][k^8(n&7)]
__device__ unsigned short g_Wl[CC * CC];          // Wv bf16-lo, swizzled

// ---------------- helpers ----------------
__device__ __forceinline__ unsigned enc_key(float f) {
    unsigned u = __float_as_uint(f);
    return (u >> 31) ? ~u : (u | 0x80000000u);
}
__device__ __forceinline__ float dec_key(unsigned e) {
    return (e & 0x80000000u) ? __uint_as_float(e ^ 0x80000000u)
                             : __uint_as_float(~e);
}
__device__ __forceinline__ uint32_t smem_u32(const void* p) {
    uint32_t a;
    asm("{ .reg .u64 t; cvta.to.shared.u64 t, %1; cvt.u32.u64 %0, t; }"
        : "=r"(a) : "l"(p));
    return a;
}
__device__ __forceinline__ void bf16_split(float v, unsigned short& h,
                                           unsigned short& l) {
    __nv_bfloat16 hh = __float2bfloat16(v);
    h = __bfloat16_as_ushort(hh);
    float r = v - __bfloat162float(hh);
    l = __bfloat16_as_ushort(__float2bfloat16(r));
}
__device__ __forceinline__ void ldmA(uint32_t* a, uint32_t addr) {
    asm volatile("ldmatrix.sync.aligned.m8n8.x4.trans.shared.b16 "
                 "{%0,%1,%2,%3}, [%4];"
                 : "=r"(a[0]), "=r"(a[1]), "=r"(a[2]), "=r"(a[3]) : "r"(addr));
}
__device__ __forceinline__ void ldmB(uint32_t* b, uint32_t addr) {
    asm volatile("ldmatrix.sync.aligned.m8n8.x2.shared.b16 {%0,%1}, [%2];"
                 : "=r"(b[0]), "=r"(b[1]) : "r"(addr));
}
__device__ __forceinline__ void mma_bf16(float* c, const uint32_t* a,
                                         const uint32_t* b) {
    asm volatile("mma.sync.aligned.m16n8k16.row.col.f32.bf16.bf16.f32 "
                 "{%0,%1,%2,%3}, {%4,%5,%6,%7}, {%8,%9}, {%0,%1,%2,%3};"
                 : "+f"(c[0]), "+f"(c[1]), "+f"(c[2]), "+f"(c[3])
                 : "r"(a[0]), "r"(a[1]), "r"(a[2]), "r"(a[3]),
                   "r"(b[0]), "r"(b[1]));
}

// ---------------- kernel 0: zero scratch ----------------
__global__ void k_zero() {
    int t = threadIdx.x;
    if (t < CC)  { g_s[0][t] = 0.f; g_s[1][t] = 0.f; }
    if (t < HWD) {
        g_mh[0][t] = 0.f; g_mh[1][t] = 0.f;
        g_mw[0][t] = 0.f; g_mw[1][t] = 0.f;
        g_md[0][t] = 0.f; g_md[1][t] = 0.f;
    }
    if (t < BB) { g_maxkey[t] = 0u; g_sumexp[t] = 0.f; }
}

// ---------------- kernel W: split Wv into bf16 hi/lo, swizzled ----------------
__global__ void k_wsplit(const float* __restrict__ Wv) {
    int i = blockIdx.x * 256 + threadIdx.x;
    if (i >= CC * CC) return;
    int n = i >> 6, k = i & 63;
    unsigned short h, l;
    bf16_split(Wv[i], h, l);
    int ks = k ^ (8 * (n & 7));
    g_Wh[n * 64 + ks] = h;
    g_Wl[n * 64 + ks] = l;
}

// ---------------- kernel 1: masked reductions ----------------
__global__ void __launch_bounds__(256) k_reduce(const float* __restrict__ x,
                                                const float* __restrict__ mask) {
    const int b   = blockIdx.y;
    const float* xb = x    + (size_t)b * CC * NVOX;
    const float* mb = mask + (size_t)b * NVOX;
    __shared__ float ss[CC];
    __shared__ float sh[HWD], sw[HWD], sd[HWD];
    const int tid = threadIdx.x;
    for (int i = tid; i < CC;  i += 256) ss[i] = 0.f;
    for (int i = tid; i < HWD; i += 256) { sh[i] = 0.f; sw[i] = 0.f; sd[i] = 0.f; }
    __syncthreads();

    float acc[CC];
    #pragma unroll
    for (int c = 0; c < CC; c++) acc[c] = 0.f;

    const int nPairs = NVOX / 2;
    for (int p = blockIdx.x * 256 + tid; p < nPairs; p += gridDim.x * 256) {
        const int n = 2 * p;
        const float2 m2 = ((const float2*)mb)[p];
        const int d = n & 63, w = (n >> 6) & 63, h = n >> 12;
        float wsum = m2.x + m2.y;
        #pragma unroll
        for (int o = 16; o; o >>= 1) wsum += __shfl_xor_sync(0xffffffffu, wsum, o);
        if ((tid & 31) == 0) { atomicAdd(&sh[h], wsum); atomicAdd(&sw[w], wsum); }
        atomicAdd(&sd[d],     m2.x);
        atomicAdd(&sd[d + 1], m2.y);
        #pragma unroll
        for (int c = 0; c < CC; c++) {
            const float2 v = ((const float2*)(xb + (size_t)c * NVOX))[p];
            acc[c] += m2.x * v.x + m2.y * v.y;
        }
    }
    #pragma unroll
    for (int c = 0; c < CC; c++) {
        float v = acc[c];
        #pragma unroll
        for (int o = 16; o; o >>= 1) v += __shfl_xor_sync(0xffffffffu, v, o);
        if ((tid & 31) == 0) atomicAdd(&ss[c], v);
    }
    __syncthreads();
    for (int i = tid; i < CC;  i += 256) atomicAdd(&g_s[b][i], ss[i]);
    for (int i = tid; i < HWD; i += 256) {
        atomicAdd(&g_mh[b][i], sh[i]);
        atomicAdd(&g_mw[b][i], sw[i]);
        atomicAdd(&g_md[b][i], sd[i]);
    }
}

// ---------------- kernel 2: tiny prep ----------------
__global__ void k_prep(const float* __restrict__ Wk, const float* __restrict__ bk,
                       const float* __restrict__ Wq, const float* __restrict__ bq,
                       const float* __restrict__ h_tab, const float* __restrict__ w_tab,
                       const float* __restrict__ d_tab) {
    const int b = blockIdx.x;
    const int t = threadIdx.x;
    __shared__ float qs[CC];
    __shared__ float Msh;
    if (t == 0) {
        float M = 0.f;
        for (int h = 0; h < HWD; h++) M += g_mh[b][h];
        Msh = M; g_M[b] = M;
    }
    __syncthreads();
    {
        float a = 0.f;
        for (int c = 0; c < CC;  c++) a += Wq[t * CC + c] * g_s[b][c];
        for (int h = 0; h < HWD; h++) a += g_mh[b][h] * h_tab[h * CC + t];
        for (int w = 0; w < HWD; w++) a += g_mw[b][w] * w_tab[w * CC + t];
        for (int d = 0; d < HWD; d++) a += g_md[b][d] * d_tab[d * CC + t];
        qs[t] = a / Msh + bq[t];
    }
    __syncthreads();
    {
        float a = 0.f;
        for (int ck = 0; ck < CC; ck++) a += qs[ck] * Wk[ck * CC + t];
        g_u[b][t] = a;
    }
    if (t == 0) {
        float a = 0.f;
        for (int ck = 0; ck < CC; ck++) a += qs[ck] * bk[ck];
        g_c0[b] = a;
    }
    {
        float a1 = 0.f, a2 = 0.f, a3 = 0.f;
        for (int ck = 0; ck < CC; ck++) {
            const float q = qs[ck];
            a1 += q * h_tab[t * CC + ck];
            a2 += q * w_tab[t * CC + ck];
            a3 += q * d_tab[t * CC + ck];
        }
        g_qh[b][t] = a1; g_qw[b][t] = a2; g_qd[b][t] = a3;
    }
}

// ---------------- kernel 3: logits + global max ----------------
__global__ void __launch_bounds__(256) k_logits(const float* __restrict__ x) {
    const int b = blockIdx.y;
    __shared__ float us[CC];
    __shared__ unsigned smax;
    const int tid = threadIdx.x;
    if (tid < CC) us[tid] = g_u[b][tid];
    if (tid == 0) smax = 0u;
    __syncthreads();
    const float* xb = x + (size_t)b * CC * NVOX;
    const float  c0 = g_c0[b];
    const int p = blockIdx.x * 256 + tid;
    const int n = 2 * p;
    float l0 = c0, l1 = c0;
    #pragma unroll
    for (int c = 0; c < CC; c++) {
        const float2 v = ((const float2*)(xb + (size_t)c * NVOX))[p];
        const float u = us[c];
        l0 += u * v.x;
        l1 += u * v.y;
    }
    const int d = n & 63, w = (n >> 6) & 63, h = n >> 12;
    const float pw = g_qh[b][h] + g_qw[b][w];
    l0 = (l0 + pw + g_qd[b][d])     * 0.125f;
    l1 = (l1 + pw + g_qd[b][d + 1]) * 0.125f;
    ((float2*)&g_logits[b][0])[p] = make_float2(l0, l1);
    float mx = fmaxf(l0, l1);
    #pragma unroll
    for (int o = 16; o; o >>= 1) mx = fmaxf(mx, __shfl_xor_sync(0xffffffffu, mx, o));
    if ((tid & 31) == 0) atomicMax(&smax, enc_key(mx));
    __syncthreads();
    if (tid == 0) atomicMax(&g_maxkey[b], smax);
}

// ---------------- kernel 4: exp + sum ----------------
__global__ void __launch_bounds__(256) k_expsum() {
    const int b = blockIdx.y;
    const float mx = dec_key(g_maxkey[b]);
    const int i = blockIdx.x * 256 + threadIdx.x;
    float2* lp = (float2*)&g_logits[b][0];
    const float2 l = lp[i];
    const float p0 = expf(l.x - mx), p1 = expf(l.y - mx);
    lp[i] = make_float2(p0, p1);
    float s = p0 + p1;
    #pragma unroll
    for (int o = 16; o; o >>= 1) s += __shfl_xor_sync(0xffffffffu, s, o);
    __shared__ float ws[8];
    const int wid = threadIdx.x >> 5;
    if ((threadIdx.x & 31) == 0) ws[wid] = s;
    __syncthreads();
    if (threadIdx.x == 0) {
        float t = 0.f;
        #pragma unroll
        for (int j = 0; j < 8; j++) t += ws[j];
        atomicAdd(&g_sumexp[b], t);
    }
}

// ---------------- kernel 5: vals GEMM on mma.sync bf16 (3-term split) ----------
// out[co][v] = sc_v * (sum_c Wv[co][c] x[c][v] + bv[co]),  sc = M*p/sumexp
// Block tile: 256 vox (M) x 64 co (N), K=64.  8 warps, each 32 vox rows.
// Smem: Xh/Xl [c][v-swizzled] bf16, Wh/Wl [n][k-swizzled] bf16; Ds overlay fp32.
#define SM_XH 0
#define SM_XL 32768
#define SM_WH 65536
#define SM_WL 73728
#define OUT_SMEM_DYN 81920

__global__ void __launch_bounds__(256, 2) k_out_mma(const float* __restrict__ x,
                                                    const float* __restrict__ bv,
                                                    float* __restrict__ out) {
    extern __shared__ char dsm[];
    __shared__ float sc_s[TILE_V];
    __shared__ float s_bv[CC];

    const int tid = threadIdx.x;
    const int b   = blockIdx.y;
    const int n0  = blockIdx.x * TILE_V;
    const uint32_t sbase = smem_u32(dsm);

    unsigned short* Xh = (unsigned short*)(dsm + SM_XH);
    unsigned short* Xl = (unsigned short*)(dsm + SM_XL);

    // weights (swizzled, identical layout) + bias
    {
        const uint4* wh = (const uint4*)g_Wh;
        const uint4* wl = (const uint4*)g_Wl;
        uint4* dh = (uint4*)(dsm + SM_WH);
        uint4* dl = (uint4*)(dsm + SM_WL);
        for (int i = tid; i < 512; i += 256) { dh[i] = wh[i]; dl[i] = wl[i]; }
        if (tid < CC) s_bv[tid] = bv[tid];
    }
    // per-vox scale (p already exp'd)
    {
        const float scl = g_M[b] / g_sumexp[b];
        if (tid < 64) {
            float4 pv = *(const float4*)&g_logits[b][n0 + tid * 4];
            sc_s[tid * 4 + 0] = scl * pv.x;
            sc_s[tid * 4 + 1] = scl * pv.y;
            sc_s[tid * 4 + 2] = scl * pv.z;
            sc_s[tid * 4 + 3] = scl * pv.w;
        }
    }
    // x tile -> bf16 hi/lo, swizzled: elem (c, v) at [c*256 + (v ^ 8*(c&7))]
    {
        const float* xb = x + (size_t)b * CC * NVOX + n0;
        const int v = (tid & 63) * 4;
        #pragma unroll 4
        for (int ph = 0; ph < 16; ph++) {
            const int c = ph * 4 + (tid >> 6);
            const float4 xv = *(const float4*)&xb[(size_t)c * NVOX + v];
            unsigned short h0, h1, h2, h3, l0, l1, l2, l3;
            bf16_split(xv.x, h0, l0);
            bf16_split(xv.y, h1, l1);
            bf16_split(xv.z, h2, l2);
            bf16_split(xv.w, h3, l3);
            const int off = c * 256 + (v ^ (8 * (c & 7)));
            uint2 hp, lp;
            hp.x = (uint32_t)h0 | ((uint32_t)h1 << 16);
            hp.y = (uint32_t)h2 | ((uint32_t)h3 << 16);
            lp.x = (uint32_t)l0 | ((uint32_t)l1 << 16);
            lp.y = (uint32_t)l2 | ((uint32_t)l3 << 16);
            *(uint2*)&Xh[off] = hp;
            *(uint2*)&Xl[off] = lp;
        }
    }
    __syncthreads();

    // ---- mma mainloop ----
    const int wrp  = tid >> 5;
    const int lane = tid & 31;
    const int v0   = wrp * 32;

    float acc[2][8][4];
    #pragma unroll
    for (int mi = 0; mi < 2; mi++)
        #pragma unroll
        for (int ni = 0; ni < 8; ni++)
            #pragma unroll
            for (int r = 0; r < 4; r++) acc[mi][ni][r] = 0.f;

    // A ldmatrix address (per lane), as function of (mi, ki):
    //   sub = lane>>3: 0:(c=k0+j,   v=v0m)   1:(c=k0+j,   v=v0m+8)
    //                  2:(c=k0+8+j, v=v0m)   3:(c=k0+8+j, v=v0m+8)
    const int jA   = lane & 7;
    const int sub  = lane >> 3;
    const int cOfA = (sub >> 1) * 8 + jA;          // within k-tile
    const int vOfA = (sub & 1) * 8;                // within m-tile
    // B ldmatrix: j2 = lane&7, sel = (lane>>3)&1: (n = n0t+j2, kchunk = k0+8*sel)
    const int jB   = lane & 7;
    const int selB = (lane >> 3) & 1;

    #pragma unroll
    for (int ki = 0; ki < 4; ki++) {
        const int k0 = ki * 16;
        uint32_t Ah[2][4], Al[2][4];
        #pragma unroll
        for (int mi = 0; mi < 2; mi++) {
            const int c = k0 + cOfA;
            const int v = v0 + mi * 16 + vOfA;
            const uint32_t off = (uint32_t)(c * 256 + (v ^ (8 * (c & 7)))) * 2u;
            ldmA(Ah[mi], sbase + SM_XH + off);
            ldmA(Al[mi], sbase + SM_XL + off);
        }
        #pragma unroll
        for (int ni = 0; ni < 8; ni++) {
            const int n = ni * 8 + jB;
            const int k = k0 + 8 * selB;
            const uint32_t off = (uint32_t)(n * 64 + (k ^ (8 * (n & 7)))) * 2u;
            uint32_t Bh[2], Bl[2];
            ldmB(Bh, sbase + SM_WH + off);
            ldmB(Bl, sbase + SM_WL + off);
            #pragma unroll
            for (int mi = 0; mi < 2; mi++) {
                mma_bf16(acc[mi][ni], Ah[mi], Bh);
                mma_bf16(acc[mi][ni], Al[mi], Bh);
                mma_bf16(acc[mi][ni], Ah[mi], Bl);
            }
        }
    }
    __syncthreads();           // done with Xh/Xl/W smem; overlay Ds

    // ---- stage D to smem (stride 260 floats: conflict-free STS) ----
    float* Ds = (float*)dsm;
    {
        const int g = lane >> 2, t4 = lane & 3;
        #pragma unroll
        for (int mi = 0; mi < 2; mi++) {
            const int m = v0 + mi * 16 + g;
            #pragma unroll
            for (int ni = 0; ni < 8; ni++) {
                const int n = ni * 8 + t4 * 2;
                Ds[n * 260 + m]           = acc[mi][ni][0];
                Ds[(n + 1) * 260 + m]     = acc[mi][ni][1];
                Ds[n * 260 + m + 8]       = acc[mi][ni][2];
                Ds[(n + 1) * 260 + m + 8] = acc[mi][ni][3];
            }
        }
    }
    __syncthreads();

    // ---- epilogue: scale + bias, coalesced float4 stores ----
    {
        const int co = tid >> 2;
        const float bvv = s_bv[co];
        float* orow = out + ((size_t)(b * CC + co)) * NVOX + n0;
        #pragma unroll 4
        for (int j = 0; j < 16; j++) {
            const int v = (tid & 3) * 4 + j * 16;
            float4 dv = *(const float4*)&Ds[co * 260 + v];
            dv.x = (dv.x + bvv) * sc_s[v + 0];
            dv.y = (dv.y + bvv) * sc_s[v + 1];
            dv.z = (dv.z + bvv) * sc_s[v + 2];
            dv.w = (dv.w + bvv) * sc_s[v + 3];
            *(float4*)&orow[v] = dv;
        }
    }
}

// ---------------- host launcher ----------------
extern "C" void kernel_launch(void* const* d_in, const int* in_sizes, int n_in,
                              void* d_out, int out_size) {
    const float* x     = (const float*)d_in[0];
    const float* mask  = (const float*)d_in[1];
    const float* Wk    = (const float*)d_in[2];
    const float* bk    = (const float*)d_in[3];
    const float* Wv    = (const float*)d_in[4];
    const float* bv    = (const float*)d_in[5];
    const float* Wq    = (const float*)d_in[6];
    const float* bq    = (const float*)d_in[7];
    const float* h_tab = (const float*)d_in[8];
    const float* w_tab = (const float*)d_in[9];
    const float* d_tab = (const float*)d_in[10];
    float* out = (float*)d_out;

    cudaFuncSetAttribute(k_out_mma, cudaFuncAttributeMaxDynamicSharedMemorySize,
                         OUT_SMEM_DYN);

    k_zero   <<<1, 128>>>();
    k_wsplit <<<16, 256>>>(Wv);
    k_reduce <<<dim3(256, BB), 256>>>(x, mask);
    k_prep   <<<BB, 64>>>(Wk, bk, Wq, bq, h_tab, w_tab, d_tab);
    k_logits <<<dim3(NVOX / 512, BB), 256>>>(x);
    k_expsum <<<dim3(NVOX / 512, BB), 256>>>();
    k_out_mma<<<dim3(NVOX / TILE_V, BB), 256, OUT_SMEM_DYN>>>(x, bv, out);

    // output tuple tail: mask passthrough
    cudaMemcpyAsync(out + (size_t)BB * CC * NVOX, mask,
                    (size_t)BB * NVOX * sizeof(float),
                    cudaMemcpyDeviceToDevice, 0);
}

// round 4
// speedup vs baseline: 1.1869x; 1.0291x over previous
#include <cuda_runtime.h>
#include <cuda_bf16.h>
#include <cstdint>

#define BB 2
#define CC 64
#define HWD 64
#define NVOX (HWD*HWD*HWD)   /* 262144 */
#define TILE_V 256

// ---------------- device scratch (static, no allocation) ----------------
__device__ float    g_s[BB][CC];
__device__ float    g_mh[BB][HWD];
__device__ float    g_mw[BB][HWD];
__device__ float    g_md[BB][HWD];
__device__ float    g_M[BB];
__device__ float    g_u[BB][CC];
__device__ float    g_c0[BB];
__device__ float    g_qh[BB][HWD];
__device__ float    g_qw[BB][HWD];
__device__ float    g_qd[BB][HWD];
__device__ unsigned g_maxkey[BB];
__device__ float    g_sumexp[BB];
__device__ float    g_logits[BB][NVOX];           // logits, then exp(l-max)
__device__ unsigned short g_Wh[CC * CC];          // Wv bf16-hi, swizzled [n][k^8(n&7)]
__device__ unsigned short g_Wl[CC * CC];          // Wv bf16-lo, swizzled

// ---------------- helpers ----------------
__device__ __forceinline__ unsigned enc_key(float f) {
    unsigned u = __float_as_uint(f);
    return (u >> 31) ? ~u : (u | 0x80000000u);
}
__device__ __forceinline__ float dec_key(unsigned e) {
    return (e & 0x80000000u) ? __uint_as_float(e ^ 0x80000000u)
                             : __uint_as_float(~e);
}
__device__ __forceinline__ uint32_t smem_u32(const void* p) {
    uint32_t a;
    asm("{ .reg .u64 t; cvta.to.shared.u64 t, %1; cvt.u32.u64 %0, t; }"
        : "=r"(a) : "l"(p));
    return a;
}
__device__ __forceinline__ void bf16_split(float v, unsigned short& h,
                                           unsigned short& l) {
    __nv_bfloat16 hh = __float2bfloat16(v);
    h = __bfloat16_as_ushort(hh);
    float r = v - __bfloat162float(hh);
    l = __bfloat16_as_ushort(__float2bfloat16(r));
}
__device__ __forceinline__ void ldmA(uint32_t* a, uint32_t addr) {
    asm volatile("ldmatrix.sync.aligned.m8n8.x4.trans.shared.b16 "
                 "{%0,%1,%2,%3}, [%4];"
                 : "=r"(a[0]), "=r"(a[1]), "=r"(a[2]), "=r"(a[3]) : "r"(addr));
}
__device__ __forceinline__ void ldmB(uint32_t* b, uint32_t addr) {
    asm volatile("ldmatrix.sync.aligned.m8n8.x2.shared.b16 {%0,%1}, [%2];"
                 : "=r"(b[0]), "=r"(b[1]) : "r"(addr));
}
__device__ __forceinline__ void mma_bf16(float* c, const uint32_t* a,
                                         const uint32_t* b) {
    asm volatile("mma.sync.aligned.m16n8k16.row.col.f32.bf16.bf16.f32 "
                 "{%0,%1,%2,%3}, {%4,%5,%6,%7}, {%8,%9}, {%0,%1,%2,%3};"
                 : "+f"(c[0]), "+f"(c[1]), "+f"(c[2]), "+f"(c[3])
                 : "r"(a[0]), "r"(a[1]), "r"(a[2]), "r"(a[3]),
                   "r"(b[0]), "r"(b[1]));
}

// ---------------- kernel W: zero scratch + split Wv (merged) ----------------
__global__ void k_wsplit(const float* __restrict__ Wv) {
    const int tid = threadIdx.x;
    if (blockIdx.x == 16) {       // zeroing block
        if (tid < CC)  { g_s[0][tid] = 0.f; g_s[1][tid] = 0.f; }
        if (tid < HWD) {
            g_mh[0][tid] = 0.f; g_mh[1][tid] = 0.f;
            g_mw[0][tid] = 0.f; g_mw[1][tid] = 0.f;
            g_md[0][tid] = 0.f; g_md[1][tid] = 0.f;
        }
        if (tid < BB) { g_maxkey[tid] = 0u; g_sumexp[tid] = 0.f; }
        return;
    }
    int i = blockIdx.x * 256 + tid;
    int n = i >> 6, k = i & 63;
    unsigned short h, l;
    bf16_split(Wv[i], h, l);
    int ks = k ^ (8 * (n & 7));
    g_Wh[n * 64 + ks] = h;
    g_Wl[n * 64 + ks] = l;
}

// ---------------- kernel 1: masked reductions ----------------
__global__ void __launch_bounds__(256) k_reduce(const float* __restrict__ x,
                                                const float* __restrict__ mask) {
    const int b   = blockIdx.y;
    const float* xb = x    + (size_t)b * CC * NVOX;
    const float* mb = mask + (size_t)b * NVOX;
    __shared__ float ss[CC];
    __shared__ float sh[HWD], sw[HWD], sd[HWD];
    const int tid = threadIdx.x;
    for (int i = tid; i < CC;  i += 256) ss[i] = 0.f;
    for (int i = tid; i < HWD; i += 256) { sh[i] = 0.f; sw[i] = 0.f; sd[i] = 0.f; }
    __syncthreads();

    float acc[CC];
    #pragma unroll
    for (int c = 0; c < CC; c++) acc[c] = 0.f;

    const int nPairs = NVOX / 2;
    for (int p = blockIdx.x * 256 + tid; p < nPairs; p += gridDim.x * 256) {
        const int n = 2 * p;
        const float2 m2 = ((const float2*)mb)[p];
        const int d = n & 63, w = (n >> 6) & 63, h = n >> 12;
        float wsum = m2.x + m2.y;
        #pragma unroll
        for (int o = 16; o; o >>= 1) wsum += __shfl_xor_sync(0xffffffffu, wsum, o);
        if ((tid & 31) == 0) { atomicAdd(&sh[h], wsum); atomicAdd(&sw[w], wsum); }
        atomicAdd(&sd[d],     m2.x);
        atomicAdd(&sd[d + 1], m2.y);
        #pragma unroll
        for (int c = 0; c < CC; c++) {
            const float2 v = ((const float2*)(xb + (size_t)c * NVOX))[p];
            acc[c] += m2.x * v.x + m2.y * v.y;
        }
    }
    #pragma unroll
    for (int c = 0; c < CC; c++) {
        float v = acc[c];
        #pragma unroll
        for (int o = 16; o; o >>= 1) v += __shfl_xor_sync(0xffffffffu, v, o);
        if ((tid & 31) == 0) atomicAdd(&ss[c], v);
    }
    __syncthreads();
    for (int i = tid; i < CC;  i += 256) atomicAdd(&g_s[b][i], ss[i]);
    for (int i = tid; i < HWD; i += 256) {
        atomicAdd(&g_mh[b][i], sh[i]);
        atomicAdd(&g_mw[b][i], sw[i]);
        atomicAdd(&g_md[b][i], sd[i]);
    }
}

// ---------------- kernel 2: prep (parallelized: 256 thr = 64 outputs x 4 slices) ----
__global__ void __launch_bounds__(256) k_prep(const float* __restrict__ Wk,
                                              const float* __restrict__ bk,
                                              const float* __restrict__ Wq,
                                              const float* __restrict__ bq,
                                              const float* __restrict__ h_tab,
                                              const float* __restrict__ w_tab,
                                              const float* __restrict__ d_tab) {
    const int b   = blockIdx.x;
    const int tid = threadIdx.x;
    const int t   = tid >> 2;         // output index 0..63
    const int sl  = tid & 3;          // slice 0..3 (16 inner elems each)
    __shared__ float qs[CC];
    __shared__ float red[CC];
    __shared__ float Msh;

    if (tid < HWD) red[tid] = g_mh[b][tid];
    __syncthreads();
    if (tid == 0) {
        float M = 0.f;
        #pragma unroll
        for (int i = 0; i < HWD; i++) M += red[i];
        Msh = M; g_M[b] = M;
    }
    __syncthreads();

    // q[t] = (Wq.s + mh.h_tab + mw.w_tab + md.d_tab)/M + bq
    {
        float a = 0.f;
        #pragma unroll
        for (int i = 0; i < 16; i++) {
            const int c = sl * 16 + i;
            a += Wq[t * CC + c] * g_s[b][c];
            a += g_mh[b][c] * h_tab[c * CC + t];
            a += g_mw[b][c] * w_tab[c * CC + t];
            a += g_md[b][c] * d_tab[c * CC + t];
        }
        a += __shfl_xor_sync(0xffffffffu, a, 1);
        a += __shfl_xor_sync(0xffffffffu, a, 2);
        if (sl == 0) qs[t] = a / Msh + bq[t];
    }
    __syncthreads();

    // u, qh, qw, qd
    {
        float u = 0.f, a1 = 0.f, a2 = 0.f, a3 = 0.f;
        #pragma unroll
        for (int i = 0; i < 16; i++) {
            const int ck = sl * 16 + i;
            const float q = qs[ck];
            u  += q * Wk[ck * CC + t];
            a1 += q * h_tab[t * CC + ck];
            a2 += q * w_tab[t * CC + ck];
            a3 += q * d_tab[t * CC + ck];
        }
        u  += __shfl_xor_sync(0xffffffffu, u, 1);
        u  += __shfl_xor_sync(0xffffffffu, u, 2);
        a1 += __shfl_xor_sync(0xffffffffu, a1, 1);
        a1 += __shfl_xor_sync(0xffffffffu, a1, 2);
        a2 += __shfl_xor_sync(0xffffffffu, a2, 1);
        a2 += __shfl_xor_sync(0xffffffffu, a2, 2);
        a3 += __shfl_xor_sync(0xffffffffu, a3, 1);
        a3 += __shfl_xor_sync(0xffffffffu, a3, 2);
        if (sl == 0) {
            g_u[b][t]  = u;
            g_qh[b][t] = a1; g_qw[b][t] = a2; g_qd[b][t] = a3;
        }
    }
    // c0 = q . bk
    if (tid < CC) red[tid] = qs[tid] * bk[tid];
    __syncthreads();
    if (tid == 0) {
        float a = 0.f;
        #pragma unroll
        for (int i = 0; i < CC; i++) a += red[i];
        g_c0[b] = a;
    }
}

// ---------------- kernel 3: logits + global max ----------------
__global__ void __launch_bounds__(256) k_logits(const float* __restrict__ x) {
    const int b = blockIdx.y;
    __shared__ float us[CC];
    __shared__ unsigned smax;
    const int tid = threadIdx.x;
    if (tid < CC) us[tid] = g_u[b][tid];
    if (tid == 0) smax = 0u;
    __syncthreads();
    const float* xb = x + (size_t)b * CC * NVOX;
    const float  c0 = g_c0[b];
    const int p = blockIdx.x * 256 + tid;
    const int n = 2 * p;
    float l0 = c0, l1 = c0;
    #pragma unroll
    for (int c = 0; c < CC; c++) {
        const float2 v = ((const float2*)(xb + (size_t)c * NVOX))[p];
        const float u = us[c];
        l0 += u * v.x;
        l1 += u * v.y;
    }
    const int d = n & 63, w = (n >> 6) & 63, h = n >> 12;
    const float pw = g_qh[b][h] + g_qw[b][w];
    l0 = (l0 + pw + g_qd[b][d])     * 0.125f;
    l1 = (l1 + pw + g_qd[b][d + 1]) * 0.125f;
    ((float2*)&g_logits[b][0])[p] = make_float2(l0, l1);
    float mx = fmaxf(l0, l1);
    #pragma unroll
    for (int o = 16; o; o >>= 1) mx = fmaxf(mx, __shfl_xor_sync(0xffffffffu, mx, o));
    if ((tid & 31) == 0) atomicMax(&smax, enc_key(mx));
    __syncthreads();
    if (tid == 0) atomicMax(&g_maxkey[b], smax);
}

// ---------------- kernel 4: exp + sum ----------------
__global__ void __launch_bounds__(256) k_expsum() {
    const int b = blockIdx.y;
    const float mx = dec_key(g_maxkey[b]);
    const int i = blockIdx.x * 256 + threadIdx.x;
    float2* lp = (float2*)&g_logits[b][0];
    const float2 l = lp[i];
    const float p0 = expf(l.x - mx), p1 = expf(l.y - mx);
    lp[i] = make_float2(p0, p1);
    float s = p0 + p1;
    #pragma unroll
    for (int o = 16; o; o >>= 1) s += __shfl_xor_sync(0xffffffffu, s, o);
    __shared__ float ws[8];
    const int wid = threadIdx.x >> 5;
    if ((threadIdx.x & 31) == 0) ws[wid] = s;
    __syncthreads();
    if (threadIdx.x == 0) {
        float t = 0.f;
        #pragma unroll
        for (int j = 0; j < 8; j++) t += ws[j];
        atomicAdd(&g_sumexp[b], t);
    }
}

// ---------------- kernel 5: vals GEMM on mma.sync bf16 (3-term split) ----------
// out[co][v] = sc_v * (sum_c Wv[co][c] x[c][v] + bv[co]),  sc = M*p/sumexp
// Block tile: 256 vox (M) x 64 co (N), K=64.  8 warps, each 32 vox rows.
#define SM_XH 0
#define SM_XL 32768
#define SM_WH 65536
#define SM_WL 73728
#define OUT_SMEM_DYN 81920

__global__ void __launch_bounds__(256, 2) k_out_mma(const float* __restrict__ x,
                                                    const float* __restrict__ bv,
                                                    float* __restrict__ out) {
    extern __shared__ char dsm[];
    __shared__ float sc_s[TILE_V];
    __shared__ float s_bv[CC];

    const int tid = threadIdx.x;
    const int b   = blockIdx.y;
    const int n0  = blockIdx.x * TILE_V;
    const uint32_t sbase = smem_u32(dsm);

    unsigned short* Xh = (unsigned short*)(dsm + SM_XH);
    unsigned short* Xl = (unsigned short*)(dsm + SM_XL);

    {
        const uint4* wh = (const uint4*)g_Wh;
        const uint4* wl = (const uint4*)g_Wl;
        uint4* dh = (uint4*)(dsm + SM_WH);
        uint4* dl = (uint4*)(dsm + SM_WL);
        for (int i = tid; i < 512; i += 256) { dh[i] = wh[i]; dl[i] = wl[i]; }
        if (tid < CC) s_bv[tid] = bv[tid];
    }
    {
        const float scl = g_M[b] / g_sumexp[b];
        if (tid < 64) {
            float4 pv = *(const float4*)&g_logits[b][n0 + tid * 4];
            sc_s[tid * 4 + 0] = scl * pv.x;
            sc_s[tid * 4 + 1] = scl * pv.y;
            sc_s[tid * 4 + 2] = scl * pv.z;
            sc_s[tid * 4 + 3] = scl * pv.w;
        }
    }
    {
        const float* xb = x + (size_t)b * CC * NVOX + n0;
        const int v = (tid & 63) * 4;
        #pragma unroll 4
        for (int ph = 0; ph < 16; ph++) {
            const int c = ph * 4 + (tid >> 6);
            const float4 xv = *(const float4*)&xb[(size_t)c * NVOX + v];
            unsigned short h0, h1, h2, h3, l0, l1, l2, l3;
            bf16_split(xv.x, h0, l0);
            bf16_split(xv.y, h1, l1);
            bf16_split(xv.z, h2, l2);
            bf16_split(xv.w, h3, l3);
            const int off = c * 256 + (v ^ (8 * (c & 7)));
            uint2 hp, lp;
            hp.x = (uint32_t)h0 | ((uint32_t)h1 << 16);
            hp.y = (uint32_t)h2 | ((uint32_t)h3 << 16);
            lp.x = (uint32_t)l0 | ((uint32_t)l1 << 16);
            lp.y = (uint32_t)l2 | ((uint32_t)l3 << 16);
            *(uint2*)&Xh[off] = hp;
            *(uint2*)&Xl[off] = lp;
        }
    }
    __syncthreads();

    const int wrp  = tid >> 5;
    const int lane = tid & 31;
    const int v0   = wrp * 32;

    float acc[2][8][4];
    #pragma unroll
    for (int mi = 0; mi < 2; mi++)
        #pragma unroll
        for (int ni = 0; ni < 8; ni++)
            #pragma unroll
            for (int r = 0; r < 4; r++) acc[mi][ni][r] = 0.f;

    const int jA   = lane & 7;
    const int sub  = lane >> 3;
    const int cOfA = (sub >> 1) * 8 + jA;
    const int vOfA = (sub & 1) * 8;
    const int jB   = lane & 7;
    const int selB = (lane >> 3) & 1;

    #pragma unroll
    for (int ki = 0; ki < 4; ki++) {
        const int k0 = ki * 16;
        uint32_t Ah[2][4], Al[2][4];
        #pragma unroll
        for (int mi = 0; mi < 2; mi++) {
            const int c = k0 + cOfA;
            const int v = v0 + mi * 16 + vOfA;
            const uint32_t off = (uint32_t)(c * 256 + (v ^ (8 * (c & 7)))) * 2u;
            ldmA(Ah[mi], sbase + SM_XH + off);
            ldmA(Al[mi], sbase + SM_XL + off);
        }
        #pragma unroll
        for (int ni = 0; ni < 8; ni++) {
            const int n = ni * 8 + jB;
            const int k = k0 + 8 * selB;
            const uint32_t off = (uint32_t)(n * 64 + (k ^ (8 * (n & 7)))) * 2u;
            uint32_t Bh[2], Bl[2];
            ldmB(Bh, sbase + SM_WH + off);
            ldmB(Bl, sbase + SM_WL + off);
            #pragma unroll
            for (int mi = 0; mi < 2; mi++) {
                mma_bf16(acc[mi][ni], Ah[mi], Bh);
                mma_bf16(acc[mi][ni], Al[mi], Bh);
                mma_bf16(acc[mi][ni], Ah[mi], Bl);
            }
        }
    }
    __syncthreads();           // done with Xh/Xl/W smem; overlay Ds

    float* Ds = (float*)dsm;
    {
        const int g = lane >> 2, t4 = lane & 3;
        #pragma unroll
        for (int mi = 0; mi < 2; mi++) {
            const int m = v0 + mi * 16 + g;
            #pragma unroll
            for (int ni = 0; ni < 8; ni++) {
                const int n = ni * 8 + t4 * 2;
                Ds[n * 260 + m]           = acc[mi][ni][0];
                Ds[(n + 1) * 260 + m]     = acc[mi][ni][1];
                Ds[n * 260 + m + 8]       = acc[mi][ni][2];
                Ds[(n + 1) * 260 + m + 8] = acc[mi][ni][3];
            }
        }
    }
    __syncthreads();

    {
        const int co = tid >> 2;
        const float bvv = s_bv[co];
        float* orow = out + ((size_t)(b * CC + co)) * NVOX + n0;
        #pragma unroll 4
        for (int j = 0; j < 16; j++) {
            const int v = (tid & 3) * 4 + j * 16;
            float4 dv = *(const float4*)&Ds[co * 260 + v];
            dv.x = (dv.x + bvv) * sc_s[v + 0];
            dv.y = (dv.y + bvv) * sc_s[v + 1];
            dv.z = (dv.z + bvv) * sc_s[v + 2];
            dv.w = (dv.w + bvv) * sc_s[v + 3];
            *(float4*)&orow[v] = dv;
        }
    }
}

// ---------------- host launcher ----------------
extern "C" void kernel_launch(void* const* d_in, const int* in_sizes, int n_in,
                              void* d_out, int out_size) {
    const float* x     = (const float*)d_in[0];
    const float* mask  = (const float*)d_in[1];
    const float* Wk    = (const float*)d_in[2];
    const float* bk    = (const float*)d_in[3];
    const float* Wv    = (const float*)d_in[4];
    const float* bv    = (const float*)d_in[5];
    const float* Wq    = (const float*)d_in[6];
    const float* bq    = (const float*)d_in[7];
    const float* h_tab = (const float*)d_in[8];
    const float* w_tab = (const float*)d_in[9];
    const float* d_tab = (const float*)d_in[10];
    float* out = (float*)d_out;

    cudaFuncSetAttribute(k_out_mma, cudaFuncAttributeMaxDynamicSharedMemorySize,
                         OUT_SMEM_DYN);

    k_wsplit <<<17, 256>>>(Wv);                     // includes scratch zeroing
    k_reduce <<<dim3(256, BB), 256>>>(x, mask);
    k_prep   <<<BB, 256>>>(Wk, bk, Wq, bq, h_tab, w_tab, d_tab);
    k_logits <<<dim3(NVOX / 512, BB), 256>>>(x);
    k_expsum <<<dim3(NVOX / 512, BB), 256>>>();
    k_out_mma<<<dim3(NVOX / TILE_V, BB), 256, OUT_SMEM_DYN>>>(x, bv, out);

    // output tuple tail: mask passthrough
    cudaMemcpyAsync(out + (size_t)BB * CC * NVOX, mask,
                    (size_t)BB * NVOX * sizeof(float),
                    cudaMemcpyDeviceToDevice, 0);
}

// round 5
// speedup vs baseline: 1.3356x; 1.1253x over previous
#include <cuda_runtime.h>
#include <cuda_bf16.h>
#include <cstdint>

#define BB 2
#define CC 64
#define HWD 64
#define NVOX (HWD*HWD*HWD)   /* 262144 */
#define TILE_V 128

// ---------------- device scratch (static, no allocation) ----------------
__device__ float    g_s[BB][CC];
__device__ float    g_mh[BB][HWD];
__device__ float    g_mw[BB][HWD];
__device__ float    g_md[BB][HWD];
__device__ float    g_M[BB];
__device__ float    g_u[BB][CC];
__device__ float    g_c0[BB];
__device__ float    g_qh[BB][HWD];
__device__ float    g_qw[BB][HWD];
__device__ float    g_qd[BB][HWD];
__device__ unsigned g_maxkey[BB];
__device__ float    g_sumexp[BB];
__device__ float    g_logits[BB][NVOX];           // logits, then exp(l-max)
__device__ unsigned short g_Wh[CC * CC];          // Wv bf16-hi, swizzled [n][k^8(n&7)]
__device__ unsigned short g_Wl[CC * CC];          // Wv bf16-lo, swizzled

// ---------------- helpers ----------------
__device__ __forceinline__ unsigned enc_key(float f) {
    unsigned u = __float_as_uint(f);
    return (u >> 31) ? ~u : (u | 0x80000000u);
}
__device__ __forceinline__ float dec_key(unsigned e) {
    return (e & 0x80000000u) ? __uint_as_float(e ^ 0x80000000u)
                             : __uint_as_float(~e);
}
__device__ __forceinline__ uint32_t smem_u32(const void* p) {
    uint32_t a;
    asm("{ .reg .u64 t; cvta.to.shared.u64 t, %1; cvt.u32.u64 %0, t; }"
        : "=r"(a) : "l"(p));
    return a;
}
__device__ __forceinline__ void bf16_split(float v, unsigned short& h,
                                           unsigned short& l) {
    __nv_bfloat16 hh = __float2bfloat16(v);
    h = __bfloat16_as_ushort(hh);
    float r = v - __bfloat162float(hh);
    l = __bfloat16_as_ushort(__float2bfloat16(r));
}
__device__ __forceinline__ void ldmA(uint32_t* a, uint32_t addr) {
    asm volatile("ldmatrix.sync.aligned.m8n8.x4.trans.shared.b16 "
                 "{%0,%1,%2,%3}, [%4];"
                 : "=r"(a[0]), "=r"(a[1]), "=r"(a[2]), "=r"(a[3]) : "r"(addr));
}
__device__ __forceinline__ void ldmB(uint32_t* b, uint32_t addr) {
    asm volatile("ldmatrix.sync.aligned.m8n8.x2.shared.b16 {%0,%1}, [%2];"
                 : "=r"(b[0]), "=r"(b[1]) : "r"(addr));
}
__device__ __forceinline__ void mma_bf16(float* c, const uint32_t* a,
                                         const uint32_t* b) {
    asm volatile("mma.sync.aligned.m16n8k16.row.col.f32.bf16.bf16.f32 "
                 "{%0,%1,%2,%3}, {%4,%5,%6,%7}, {%8,%9}, {%0,%1,%2,%3};"
                 : "+f"(c[0]), "+f"(c[1]), "+f"(c[2]), "+f"(c[3])
                 : "r"(a[0]), "r"(a[1]), "r"(a[2]), "r"(a[3]),
                   "r"(b[0]), "r"(b[1]));
}

// ---------------- kernel W: zero scratch + split Wv (merged) ----------------
__global__ void k_wsplit(const float* __restrict__ Wv) {
    const int tid = threadIdx.x;
    if (blockIdx.x == 16) {       // zeroing block
        if (tid < CC)  { g_s[0][tid] = 0.f; g_s[1][tid] = 0.f; }
        if (tid < HWD) {
            g_mh[0][tid] = 0.f; g_mh[1][tid] = 0.f;
            g_mw[0][tid] = 0.f; g_mw[1][tid] = 0.f;
            g_md[0][tid] = 0.f; g_md[1][tid] = 0.f;
        }
        if (tid < BB) { g_maxkey[tid] = 0u; g_sumexp[tid] = 0.f; }
        return;
    }
    int i = blockIdx.x * 256 + tid;
    int n = i >> 6, k = i & 63;
    unsigned short h, l;
    bf16_split(Wv[i], h, l);
    int ks = k ^ (8 * (n & 7));
    g_Wh[n * 64 + ks] = h;
    g_Wl[n * 64 + ks] = l;
}

// ---------------- kernel 1: masked reductions ----------------
__global__ void __launch_bounds__(256) k_reduce(const float* __restrict__ x,
                                                const float* __restrict__ mask) {
    const int b   = blockIdx.y;
    const float* xb = x    + (size_t)b * CC * NVOX;
    const float* mb = mask + (size_t)b * NVOX;
    __shared__ float ss[CC];
    __shared__ float sh[HWD], sw[HWD], sd[HWD];
    const int tid = threadIdx.x;
    for (int i = tid; i < CC;  i += 256) ss[i] = 0.f;
    for (int i = tid; i < HWD; i += 256) { sh[i] = 0.f; sw[i] = 0.f; sd[i] = 0.f; }
    __syncthreads();

    float acc[CC];
    #pragma unroll
    for (int c = 0; c < CC; c++) acc[c] = 0.f;

    const int nPairs = NVOX / 2;
    for (int p = blockIdx.x * 256 + tid; p < nPairs; p += gridDim.x * 256) {
        const int n = 2 * p;
        const float2 m2 = ((const float2*)mb)[p];
        const int d = n & 63, w = (n >> 6) & 63, h = n >> 12;
        float wsum = m2.x + m2.y;
        #pragma unroll
        for (int o = 16; o; o >>= 1) wsum += __shfl_xor_sync(0xffffffffu, wsum, o);
        if ((tid & 31) == 0) { atomicAdd(&sh[h], wsum); atomicAdd(&sw[w], wsum); }
        atomicAdd(&sd[d],     m2.x);
        atomicAdd(&sd[d + 1], m2.y);
        #pragma unroll
        for (int c = 0; c < CC; c++) {
            const float2 v = ((const float2*)(xb + (size_t)c * NVOX))[p];
            acc[c] += m2.x * v.x + m2.y * v.y;
        }
    }
    #pragma unroll
    for (int c = 0; c < CC; c++) {
        float v = acc[c];
        #pragma unroll
        for (int o = 16; o; o >>= 1) v += __shfl_xor_sync(0xffffffffu, v, o);
        if ((tid & 31) == 0) atomicAdd(&ss[c], v);
    }
    __syncthreads();
    for (int i = tid; i < CC;  i += 256) atomicAdd(&g_s[b][i], ss[i]);
    for (int i = tid; i < HWD; i += 256) {
        atomicAdd(&g_mh[b][i], sh[i]);
        atomicAdd(&g_mw[b][i], sw[i]);
        atomicAdd(&g_md[b][i], sd[i]);
    }
}

// ---------------- kernel 2: prep (256 thr = 64 outputs x 4 slices) ----------
__global__ void __launch_bounds__(256) k_prep(const float* __restrict__ Wk,
                                              const float* __restrict__ bk,
                                              const float* __restrict__ Wq,
                                              const float* __restrict__ bq,
                                              const float* __restrict__ h_tab,
                                              const float* __restrict__ w_tab,
                                              const float* __restrict__ d_tab) {
    const int b   = blockIdx.x;
    const int tid = threadIdx.x;
    const int t   = tid >> 2;
    const int sl  = tid & 3;
    __shared__ float qs[CC];
    __shared__ float red[CC];
    __shared__ float Msh;

    if (tid < HWD) red[tid] = g_mh[b][tid];
    __syncthreads();
    if (tid == 0) {
        float M = 0.f;
        #pragma unroll
        for (int i = 0; i < HWD; i++) M += red[i];
        Msh = M; g_M[b] = M;
    }
    __syncthreads();

    {
        float a = 0.f;
        #pragma unroll
        for (int i = 0; i < 16; i++) {
            const int c = sl * 16 + i;
            a += Wq[t * CC + c] * g_s[b][c];
            a += g_mh[b][c] * h_tab[c * CC + t];
            a += g_mw[b][c] * w_tab[c * CC + t];
            a += g_md[b][c] * d_tab[c * CC + t];
        }
        a += __shfl_xor_sync(0xffffffffu, a, 1);
        a += __shfl_xor_sync(0xffffffffu, a, 2);
        if (sl == 0) qs[t] = a / Msh + bq[t];
    }
    __syncthreads();

    {
        float u = 0.f, a1 = 0.f, a2 = 0.f, a3 = 0.f;
        #pragma unroll
        for (int i = 0; i < 16; i++) {
            const int ck = sl * 16 + i;
            const float q = qs[ck];
            u  += q * Wk[ck * CC + t];
            a1 += q * h_tab[t * CC + ck];
            a2 += q * w_tab[t * CC + ck];
            a3 += q * d_tab[t * CC + ck];
        }
        u  += __shfl_xor_sync(0xffffffffu, u, 1);
        u  += __shfl_xor_sync(0xffffffffu, u, 2);
        a1 += __shfl_xor_sync(0xffffffffu, a1, 1);
        a1 += __shfl_xor_sync(0xffffffffu, a1, 2);
        a2 += __shfl_xor_sync(0xffffffffu, a2, 1);
        a2 += __shfl_xor_sync(0xffffffffu, a2, 2);
        a3 += __shfl_xor_sync(0xffffffffu, a3, 1);
        a3 += __shfl_xor_sync(0xffffffffu, a3, 2);
        if (sl == 0) {
            g_u[b][t]  = u;
            g_qh[b][t] = a1; g_qw[b][t] = a2; g_qd[b][t] = a3;
        }
    }
    if (tid < CC) red[tid] = qs[tid] * bk[tid];
    __syncthreads();
    if (tid == 0) {
        float a = 0.f;
        #pragma unroll
        for (int i = 0; i < CC; i++) a += red[i];
        g_c0[b] = a;
    }
}

// ---------------- kernel 3: logits + global max ----------------
__global__ void __launch_bounds__(256) k_logits(const float* __restrict__ x) {
    const int b = blockIdx.y;
    __shared__ float us[CC];
    __shared__ unsigned smax;
    const int tid = threadIdx.x;
    if (tid < CC) us[tid] = g_u[b][tid];
    if (tid == 0) smax = 0u;
    __syncthreads();
    const float* xb = x + (size_t)b * CC * NVOX;
    const float  c0 = g_c0[b];
    const int p = blockIdx.x * 256 + tid;
    const int n = 2 * p;
    float l0 = c0, l1 = c0;
    #pragma unroll
    for (int c = 0; c < CC; c++) {
        const float2 v = ((const float2*)(xb + (size_t)c * NVOX))[p];
        const float u = us[c];
        l0 += u * v.x;
        l1 += u * v.y;
    }
    const int d = n & 63, w = (n >> 6) & 63, h = n >> 12;
    const float pw = g_qh[b][h] + g_qw[b][w];
    l0 = (l0 + pw + g_qd[b][d])     * 0.125f;
    l1 = (l1 + pw + g_qd[b][d + 1]) * 0.125f;
    ((float2*)&g_logits[b][0])[p] = make_float2(l0, l1);
    float mx = fmaxf(l0, l1);
    #pragma unroll
    for (int o = 16; o; o >>= 1) mx = fmaxf(mx, __shfl_xor_sync(0xffffffffu, mx, o));
    if ((tid & 31) == 0) atomicMax(&smax, enc_key(mx));
    __syncthreads();
    if (tid == 0) atomicMax(&g_maxkey[b], smax);
}

// ---------------- kernel 4: exp + sum ----------------
__global__ void __launch_bounds__(256) k_expsum() {
    const int b = blockIdx.y;
    const float mx = dec_key(g_maxkey[b]);
    const int i = blockIdx.x * 256 + threadIdx.x;
    float2* lp = (float2*)&g_logits[b][0];
    const float2 l = lp[i];
    const float p0 = expf(l.x - mx), p1 = expf(l.y - mx);
    lp[i] = make_float2(p0, p1);
    float s = p0 + p1;
    #pragma unroll
    for (int o = 16; o; o >>= 1) s += __shfl_xor_sync(0xffffffffu, s, o);
    __shared__ float ws[8];
    const int wid = threadIdx.x >> 5;
    if ((threadIdx.x & 31) == 0) ws[wid] = s;
    __syncthreads();
    if (threadIdx.x == 0) {
        float t = 0.f;
        #pragma unroll
        for (int j = 0; j < 8; j++) t += ws[j];
        atomicAdd(&g_sumexp[b], t);
    }
}

// ---------------- kernel 5: vals GEMM on mma.sync bf16 (3-term split) ----------
// Block tile: 128 vox (M) x 64 co (N), K=64.  8 warps, each 16 vox rows.
// smem 48KB -> 3 CTAs/SM; coalesced 512B epilogue stores.
#define SM_XH 0
#define SM_XL 16384
#define SM_WH 32768
#define SM_WL 40960
#define OUT_SMEM_DYN 49152

__global__ void __launch_bounds__(256, 3) k_out_mma(const float* __restrict__ x,
                                                    const float* __restrict__ bv,
                                                    float* __restrict__ out) {
    extern __shared__ char dsm[];
    __shared__ float sc_s[TILE_V];
    __shared__ float s_bv[CC];

    const int tid = threadIdx.x;
    const int b   = blockIdx.y;
    const int n0  = blockIdx.x * TILE_V;
    const uint32_t sbase = smem_u32(dsm);

    unsigned short* Xh = (unsigned short*)(dsm + SM_XH);
    unsigned short* Xl = (unsigned short*)(dsm + SM_XL);

    // ---- front-load x tile: 8 float4 per thread, issued before setup ALU ----
    const float* xb = x + (size_t)b * CC * NVOX + n0;
    const int vld = (tid & 31) * 4;        // vox offset (warp covers full 128-row)
    const int cld = tid >> 5;              // base channel (8 phases, stride 8)
    float4 xv[8];
    #pragma unroll
    for (int ph = 0; ph < 8; ph++)
        xv[ph] = *(const float4*)&xb[(size_t)(cld + ph * 8) * NVOX + vld];

    // ---- weights + bias + per-vox scale (overlaps x-load latency) ----
    {
        const uint4* wh = (const uint4*)g_Wh;
        const uint4* wl = (const uint4*)g_Wl;
        uint4* dh = (uint4*)(dsm + SM_WH);
        uint4* dl = (uint4*)(dsm + SM_WL);
        if (tid < 256) {
            const int i = tid;
            if (i < 512) { }
        }
        for (int i = tid; i < 512; i += 256) { dh[i] = wh[i]; dl[i] = wl[i]; }
        if (tid < CC) s_bv[tid] = bv[tid];
        const float scl = g_M[b] / g_sumexp[b];
        if (tid < 32) {
            float4 pv = *(const float4*)&g_logits[b][n0 + tid * 4];
            sc_s[tid * 4 + 0] = scl * pv.x;
            sc_s[tid * 4 + 1] = scl * pv.y;
            sc_s[tid * 4 + 2] = scl * pv.z;
            sc_s[tid * 4 + 3] = scl * pv.w;
        }
    }
    // ---- convert + swizzled store: elem (c, v) at [c*128 + (v ^ 8*(c&7))] ----
    #pragma unroll
    for (int ph = 0; ph < 8; ph++) {
        const int c = cld + ph * 8;
        unsigned short h0, h1, h2, h3, l0, l1, l2, l3;
        bf16_split(xv[ph].x, h0, l0);
        bf16_split(xv[ph].y, h1, l1);
        bf16_split(xv[ph].z, h2, l2);
        bf16_split(xv[ph].w, h3, l3);
        const int off = c * 128 + (vld ^ (8 * (c & 7)));
        uint2 hp, lp;
        hp.x = (uint32_t)h0 | ((uint32_t)h1 << 16);
        hp.y = (uint32_t)h2 | ((uint32_t)h3 << 16);
        lp.x = (uint32_t)l0 | ((uint32_t)l1 << 16);
        lp.y = (uint32_t)l2 | ((uint32_t)l3 << 16);
        *(uint2*)&Xh[off] = hp;
        *(uint2*)&Xl[off] = lp;
    }
    __syncthreads();

    // ---- mma mainloop: warp = 16 vox rows x 64 co ----
    const int wrp  = tid >> 5;
    const int lane = tid & 31;
    const int v0   = wrp * 16;

    float acc[8][4];
    #pragma unroll
    for (int ni = 0; ni < 8; ni++)
        #pragma unroll
        for (int r = 0; r < 4; r++) acc[ni][r] = 0.f;

    const int jA   = lane & 7;
    const int sub  = lane >> 3;
    const int cOfA = (sub >> 1) * 8 + jA;
    const int vOfA = (sub & 1) * 8;
    const int jB   = lane & 7;
    const int selB = (lane >> 3) & 1;

    #pragma unroll
    for (int ki = 0; ki < 4; ki++) {
        const int k0 = ki * 16;
        uint32_t Ah[4], Al[4];
        {
            const int c = k0 + cOfA;
            const int v = v0 + vOfA;
            const uint32_t off = (uint32_t)(c * 128 + (v ^ (8 * (c & 7)))) * 2u;
            ldmA(Ah, sbase + SM_XH + off);
            ldmA(Al, sbase + SM_XL + off);
        }
        #pragma unroll
        for (int ni = 0; ni < 8; ni++) {
            const int n = ni * 8 + jB;
            const int k = k0 + 8 * selB;
            const uint32_t off = (uint32_t)(n * 64 + (k ^ (8 * (n & 7)))) * 2u;
            uint32_t Bh[2], Bl[2];
            ldmB(Bh, sbase + SM_WH + off);
            ldmB(Bl, sbase + SM_WL + off);
            mma_bf16(acc[ni], Ah, Bh);
            mma_bf16(acc[ni], Al, Bh);
            mma_bf16(acc[ni], Ah, Bl);
        }
    }
    __syncthreads();           // done with Xh/Xl/W smem; overlay Ds

    // ---- stage D to smem: Ds[co][vox], row stride 132 floats ----
    float* Ds = (float*)dsm;
    {
        const int g = lane >> 2, t4 = lane & 3;
        const int m = v0 + g;
        #pragma unroll
        for (int ni = 0; ni < 8; ni++) {
            const int n = ni * 8 + t4 * 2;
            Ds[n * 132 + m]           = acc[ni][0];
            Ds[(n + 1) * 132 + m]     = acc[ni][1];
            Ds[n * 132 + m + 8]       = acc[ni][2];
            Ds[(n + 1) * 132 + m + 8] = acc[ni][3];
        }
    }
    __syncthreads();

    // ---- epilogue: warp = 8 co rows, lane covers full 128-vox row (512B stores)
    {
        const int v = lane * 4;
        const float4 sv = *(const float4*)&sc_s[v];
        #pragma unroll
        for (int r = 0; r < 8; r++) {
            const int co = wrp * 8 + r;
            const float bvv = s_bv[co];
            float4 dv = *(const float4*)&Ds[co * 132 + v];
            dv.x = (dv.x + bvv) * sv.x;
            dv.y = (dv.y + bvv) * sv.y;
            dv.z = (dv.z + bvv) * sv.z;
            dv.w = (dv.w + bvv) * sv.w;
            *(float4*)&out[((size_t)(b * CC + co)) * NVOX + n0 + v] = dv;
        }
    }
}

// ---------------- host launcher ----------------
extern "C" void kernel_launch(void* const* d_in, const int* in_sizes, int n_in,
                              void* d_out, int out_size) {
    const float* x     = (const float*)d_in[0];
    const float* mask  = (const float*)d_in[1];
    const float* Wk    = (const float*)d_in[2];
    const float* bk    = (const float*)d_in[3];
    const float* Wv    = (const float*)d_in[4];
    const float* bv    = (const float*)d_in[5];
    const float* Wq    = (const float*)d_in[6];
    const float* bq    = (const float*)d_in[7];
    const float* h_tab = (const float*)d_in[8];
    const float* w_tab = (const float*)d_in[9];
    const float* d_tab = (const float*)d_in[10];
    float* out = (float*)d_out;

    cudaFuncSetAttribute(k_out_mma, cudaFuncAttributeMaxDynamicSharedMemorySize,
                         OUT_SMEM_DYN);

    k_wsplit <<<17, 256>>>(Wv);                     // includes scratch zeroing
    k_reduce <<<dim3(256, BB), 256>>>(x, mask);
    k_prep   <<<BB, 256>>>(Wk, bk, Wq, bq, h_tab, w_tab, d_tab);
    k_logits <<<dim3(NVOX / 512, BB), 256>>>(x);
    k_expsum <<<dim3(NVOX / 512, BB), 256>>>();
    k_out_mma<<<dim3(NVOX / TILE_V, BB), 256, OUT_SMEM_DYN>>>(x, bv, out);

    // output tuple tail: mask passthrough
    cudaMemcpyAsync(out + (size_t)BB * CC * NVOX, mask,
                    (size_t)BB * NVOX * sizeof(float),
                    cudaMemcpyDeviceToDevice, 0);
}

// round 6
// speedup vs baseline: 1.3722x; 1.0274x over previous
#include <cuda_runtime.h>
#include <cuda_bf16.h>
#include <cstdint>

#define BB 2
#define CC 64
#define HWD 64
#define NVOX (HWD*HWD*HWD)   /* 262144 */
#define TILE_V 128
#define NBLK_L 512           /* k_logits blocks per batch (512 vox each) */

// ---------------- device scratch (static, no allocation) ----------------
__device__ float    g_s[BB][CC];
__device__ float    g_mh[BB][HWD];
__device__ float    g_mw[BB][HWD];
__device__ float    g_md[BB][HWD];
__device__ float    g_M[BB];
__device__ float    g_u[BB][CC];
__device__ float    g_c0[BB];
__device__ float    g_qh[BB][HWD];
__device__ float    g_qw[BB][HWD];
__device__ float    g_qd[BB][HWD];
__device__ float    g_bmax[BB][NBLK_L];
__device__ float    g_bsum[BB][NBLK_L];
__device__ float    g_gmax[BB];
__device__ float    g_scale[BB];          // M / sumexp
__device__ float    g_logits[BB][NVOX];   // raw logits
__device__ unsigned short g_Wh[CC * CC];  // Wv bf16-hi, swizzled [n][k^8(n&7)]
__device__ unsigned short g_Wl[CC * CC];  // Wv bf16-lo, swizzled

// ---------------- helpers ----------------
__device__ __forceinline__ uint32_t smem_u32(const void* p) {
    uint32_t a;
    asm("{ .reg .u64 t; cvta.to.shared.u64 t, %1; cvt.u32.u64 %0, t; }"
        : "=r"(a) : "l"(p));
    return a;
}
__device__ __forceinline__ void bf16_split(float v, unsigned short& h,
                                           unsigned short& l) {
    __nv_bfloat16 hh = __float2bfloat16(v);
    h = __bfloat16_as_ushort(hh);
    float r = v - __bfloat162float(hh);
    l = __bfloat16_as_ushort(__float2bfloat16(r));
}
// packed 2-elem bf16 hi/lo split: h = {bf16(v1),bf16(v0)}, l = residuals
__device__ __forceinline__ void bf16_split2(float v0, float v1,
                                            uint32_t& h, uint32_t& l) {
    asm("cvt.rn.bf16x2.f32 %0, %1, %2;" : "=r"(h) : "f"(v1), "f"(v0));
    const float f0 = __uint_as_float(h << 16);
    const float f1 = __uint_as_float(h & 0xffff0000u);
    const float r0 = v0 - f0;
    const float r1 = v1 - f1;
    asm("cvt.rn.bf16x2.f32 %0, %1, %2;" : "=r"(l) : "f"(r1), "f"(r0));
}
__device__ __forceinline__ void ldmA(uint32_t* a, uint32_t addr) {
    asm volatile("ldmatrix.sync.aligned.m8n8.x4.trans.shared.b16 "
                 "{%0,%1,%2,%3}, [%4];"
                 : "=r"(a[0]), "=r"(a[1]), "=r"(a[2]), "=r"(a[3]) : "r"(addr));
}
__device__ __forceinline__ void ldmB4(uint32_t* b, uint32_t addr) {
    asm volatile("ldmatrix.sync.aligned.m8n8.x4.shared.b16 {%0,%1,%2,%3}, [%4];"
                 : "=r"(b[0]), "=r"(b[1]), "=r"(b[2]), "=r"(b[3]) : "r"(addr));
}
__device__ __forceinline__ void mma_bf16(float* c, const uint32_t* a,
                                         const uint32_t* b) {
    asm volatile("mma.sync.aligned.m16n8k16.row.col.f32.bf16.bf16.f32 "
                 "{%0,%1,%2,%3}, {%4,%5,%6,%7}, {%8,%9}, {%0,%1,%2,%3};"
                 : "+f"(c[0]), "+f"(c[1]), "+f"(c[2]), "+f"(c[3])
                 : "r"(a[0]), "r"(a[1]), "r"(a[2]), "r"(a[3]),
                   "r"(b[0]), "r"(b[1]));
}

// ---------------- kernel W: zero scratch + split Wv (merged) ----------------
__global__ void k_wsplit(const float* __restrict__ Wv) {
    const int tid = threadIdx.x;
    if (blockIdx.x == 16) {       // zeroing block
        if (tid < CC)  { g_s[0][tid] = 0.f; g_s[1][tid] = 0.f; }
        if (tid < HWD) {
            g_mh[0][tid] = 0.f; g_mh[1][tid] = 0.f;
            g_mw[0][tid] = 0.f; g_mw[1][tid] = 0.f;
            g_md[0][tid] = 0.f; g_md[1][tid] = 0.f;
        }
        return;
    }
    int i = blockIdx.x * 256 + tid;
    int n = i >> 6, k = i & 63;
    unsigned short h, l;
    bf16_split(Wv[i], h, l);
    int ks = k ^ (8 * (n & 7));
    g_Wh[n * 64 + ks] = h;
    g_Wl[n * 64 + ks] = l;
}

// ---------------- kernel 1: masked reductions ----------------
__global__ void __launch_bounds__(256) k_reduce(const float* __restrict__ x,
                                                const float* __restrict__ mask) {
    const int b   = blockIdx.y;
    const float* xb = x    + (size_t)b * CC * NVOX;
    const float* mb = mask + (size_t)b * NVOX;
    __shared__ float ss[CC];
    __shared__ float sh[HWD], sw[HWD], sd[HWD];
    const int tid = threadIdx.x;
    for (int i = tid; i < CC;  i += 256) ss[i] = 0.f;
    for (int i = tid; i < HWD; i += 256) { sh[i] = 0.f; sw[i] = 0.f; sd[i] = 0.f; }
    __syncthreads();

    float acc[CC];
    #pragma unroll
    for (int c = 0; c < CC; c++) acc[c] = 0.f;

    const int nPairs = NVOX / 2;
    for (int p = blockIdx.x * 256 + tid; p < nPairs; p += gridDim.x * 256) {
        const int n = 2 * p;
        const float2 m2 = ((const float2*)mb)[p];
        const int d = n & 63, w = (n >> 6) & 63, h = n >> 12;
        float wsum = m2.x + m2.y;
        #pragma unroll
        for (int o = 16; o; o >>= 1) wsum += __shfl_xor_sync(0xffffffffu, wsum, o);
        if ((tid & 31) == 0) { atomicAdd(&sh[h], wsum); atomicAdd(&sw[w], wsum); }
        atomicAdd(&sd[d],     m2.x);
        atomicAdd(&sd[d + 1], m2.y);
        #pragma unroll
        for (int c = 0; c < CC; c++) {
            const float2 v = ((const float2*)(xb + (size_t)c * NVOX))[p];
            acc[c] += m2.x * v.x + m2.y * v.y;
        }
    }
    #pragma unroll
    for (int c = 0; c < CC; c++) {
        float v = acc[c];
        #pragma unroll
        for (int o = 16; o; o >>= 1) v += __shfl_xor_sync(0xffffffffu, v, o);
        if ((tid & 31) == 0) atomicAdd(&ss[c], v);
    }
    __syncthreads();
    for (int i = tid; i < CC;  i += 256) atomicAdd(&g_s[b][i], ss[i]);
    for (int i = tid; i < HWD; i += 256) {
        atomicAdd(&g_mh[b][i], sh[i]);
        atomicAdd(&g_mw[b][i], sw[i]);
        atomicAdd(&g_md[b][i], sd[i]);
    }
}

// ---------------- kernel 2: prep (256 thr = 64 outputs x 4 slices) ----------
__global__ void __launch_bounds__(256) k_prep(const float* __restrict__ Wk,
                                              const float* __restrict__ bk,
                                              const float* __restrict__ Wq,
                                              const float* __restrict__ bq,
                                              const float* __restrict__ h_tab,
                                              const float* __restrict__ w_tab,
                                              const float* __restrict__ d_tab) {
    const int b   = blockIdx.x;
    const int tid = threadIdx.x;
    const int t   = tid >> 2;
    const int sl  = tid & 3;
    __shared__ float qs[CC];
    __shared__ float red[CC];
    __shared__ float Msh;

    if (tid < HWD) red[tid] = g_mh[b][tid];
    __syncthreads();
    if (tid == 0) {
        float M = 0.f;
        #pragma unroll
        for (int i = 0; i < HWD; i++) M += red[i];
        Msh = M; g_M[b] = M;
    }
    __syncthreads();

    {
        float a = 0.f;
        #pragma unroll
        for (int i = 0; i < 16; i++) {
            const int c = sl * 16 + i;
            a += Wq[t * CC + c] * g_s[b][c];
            a += g_mh[b][c] * h_tab[c * CC + t];
            a += g_mw[b][c] * w_tab[c * CC + t];
            a += g_md[b][c] * d_tab[c * CC + t];
        }
        a += __shfl_xor_sync(0xffffffffu, a, 1);
        a += __shfl_xor_sync(0xffffffffu, a, 2);
        if (sl == 0) qs[t] = a / Msh + bq[t];
    }
    __syncthreads();

    {
        float u = 0.f, a1 = 0.f, a2 = 0.f, a3 = 0.f;
        #pragma unroll
        for (int i = 0; i < 16; i++) {
            const int ck = sl * 16 + i;
            const float q = qs[ck];
            u  += q * Wk[ck * CC + t];
            a1 += q * h_tab[t * CC + ck];
            a2 += q * w_tab[t * CC + ck];
            a3 += q * d_tab[t * CC + ck];
        }
        u  += __shfl_xor_sync(0xffffffffu, u, 1);
        u  += __shfl_xor_sync(0xffffffffu, u, 2);
        a1 += __shfl_xor_sync(0xffffffffu, a1, 1);
        a1 += __shfl_xor_sync(0xffffffffu, a1, 2);
        a2 += __shfl_xor_sync(0xffffffffu, a2, 1);
        a2 += __shfl_xor_sync(0xffffffffu, a2, 2);
        a3 += __shfl_xor_sync(0xffffffffu, a3, 1);
        a3 += __shfl_xor_sync(0xffffffffu, a3, 2);
        if (sl == 0) {
            g_u[b][t]  = u;
            g_qh[b][t] = a1; g_qw[b][t] = a2; g_qd[b][t] = a3;
        }
    }
    if (tid < CC) red[tid] = qs[tid] * bk[tid];
    __syncthreads();
    if (tid == 0) {
        float a = 0.f;
        #pragma unroll
        for (int i = 0; i < CC; i++) a += red[i];
        g_c0[b] = a;
    }
}

// ---------------- kernel 3: logits + block max + block expsum ----------------
__global__ void __launch_bounds__(256) k_logits(const float* __restrict__ x) {
    const int b = blockIdx.y;
    __shared__ float us[CC];
    __shared__ float wred[8];
    __shared__ float bmax_s;
    const int tid = threadIdx.x;
    if (tid < CC) us[tid] = g_u[b][tid];
    __syncthreads();
    const float* xb = x + (size_t)b * CC * NVOX;
    const float  c0 = g_c0[b];
    const int p = blockIdx.x * 256 + tid;
    const int n = 2 * p;
    float l0 = c0, l1 = c0;
    #pragma unroll
    for (int c = 0; c < CC; c++) {
        const float2 v = ((const float2*)(xb + (size_t)c * NVOX))[p];
        const float u = us[c];
        l0 += u * v.x;
        l1 += u * v.y;
    }
    const int d = n & 63, w = (n >> 6) & 63, h = n >> 12;
    const float pw = g_qh[b][h] + g_qw[b][w];
    l0 = (l0 + pw + g_qd[b][d])     * 0.125f;
    l1 = (l1 + pw + g_qd[b][d + 1]) * 0.125f;
    ((float2*)&g_logits[b][0])[p] = make_float2(l0, l1);

    // block max
    float mx = fmaxf(l0, l1);
    #pragma unroll
    for (int o = 16; o; o >>= 1) mx = fmaxf(mx, __shfl_xor_sync(0xffffffffu, mx, o));
    const int wid = tid >> 5;
    if ((tid & 31) == 0) wred[wid] = mx;
    __syncthreads();
    if (tid == 0) {
        float m = wred[0];
        #pragma unroll
        for (int j = 1; j < 8; j++) m = fmaxf(m, wred[j]);
        bmax_s = m;
    }
    __syncthreads();
    const float bm = bmax_s;

    // block sum of exp(l - bm)
    float s = expf(l0 - bm) + expf(l1 - bm);
    #pragma unroll
    for (int o = 16; o; o >>= 1) s += __shfl_xor_sync(0xffffffffu, s, o);
    if ((tid & 31) == 0) wred[wid] = s;
    __syncthreads();
    if (tid == 0) {
        float t = 0.f;
        #pragma unroll
        for (int j = 0; j < 8; j++) t += wred[j];
        g_bmax[b][blockIdx.x] = bm;
        g_bsum[b][blockIdx.x] = t;
    }
}

// ---------------- kernel 4: finish softmax stats (tiny) ----------------
__global__ void __launch_bounds__(NBLK_L) k_finish() {
    const int b = blockIdx.x;
    const int t = threadIdx.x;        // 512
    __shared__ float wred[16];
    __shared__ float gmax_s;
    const float bm = g_bmax[b][t];
    float m = bm;
    #pragma unroll
    for (int o = 16; o; o >>= 1) m = fmaxf(m, __shfl_xor_sync(0xffffffffu, m, o));
    if ((t & 31) == 0) wred[t >> 5] = m;
    __syncthreads();
    if (t == 0) {
        float g = wred[0];
        #pragma unroll
        for (int j = 1; j < 16; j++) g = fmaxf(g, wred[j]);
        gmax_s = g;
    }
    __syncthreads();
    const float gm = gmax_s;
    float s = g_bsum[b][t] * expf(bm - gm);
    #pragma unroll
    for (int o = 16; o; o >>= 1) s += __shfl_xor_sync(0xffffffffu, s, o);
    if ((t & 31) == 0) wred[t >> 5] = s;
    __syncthreads();
    if (t == 0) {
        float tot = 0.f;
        #pragma unroll
        for (int j = 0; j < 16; j++) tot += wred[j];
        g_gmax[b]  = gm;
        g_scale[b] = g_M[b] / tot;
    }
}

// ---------------- kernel 5: vals GEMM on mma.sync bf16 (3-term split) ----------
// Block tile: 128 vox (M) x 64 co (N), K=64.  8 warps, each 16 vox rows.
#define SM_XH 0
#define SM_XL 16384
#define SM_WH 32768
#define SM_WL 40960
#define OUT_SMEM_DYN 49152

__global__ void __launch_bounds__(256, 3) k_out_mma(const float* __restrict__ x,
                                                    const float* __restrict__ bv,
                                                    float* __restrict__ out) {
    extern __shared__ char dsm[];
    __shared__ float sc_s[TILE_V];
    __shared__ float s_bv[CC];

    const int tid = threadIdx.x;
    const int b   = blockIdx.y;
    const int n0  = blockIdx.x * TILE_V;
    const uint32_t sbase = smem_u32(dsm);

    unsigned short* Xh = (unsigned short*)(dsm + SM_XH);
    unsigned short* Xl = (unsigned short*)(dsm + SM_XL);

    // ---- front-load x tile: 8 float4 per thread ----
    const float* xb = x + (size_t)b * CC * NVOX + n0;
    const int vld = (tid & 31) * 4;
    const int cld = tid >> 5;
    float4 xv[8];
    #pragma unroll
    for (int ph = 0; ph < 8; ph++)
        xv[ph] = *(const float4*)&xb[(size_t)(cld + ph * 8) * NVOX + vld];

    // ---- weights + bias + per-vox softmax scale (overlaps x-load latency) ----
    {
        const uint4* wh = (const uint4*)g_Wh;
        const uint4* wl = (const uint4*)g_Wl;
        uint4* dh = (uint4*)(dsm + SM_WH);
        uint4* dl = (uint4*)(dsm + SM_WL);
        for (int i = tid; i < 512; i += 256) { dh[i] = wh[i]; dl[i] = wl[i]; }
        if (tid < CC) s_bv[tid] = bv[tid];
        if (tid < 32) {
            const float scl = g_scale[b];
            const float gm  = g_gmax[b];
            float4 pv = *(const float4*)&g_logits[b][n0 + tid * 4];
            sc_s[tid * 4 + 0] = scl * expf(pv.x - gm);
            sc_s[tid * 4 + 1] = scl * expf(pv.y - gm);
            sc_s[tid * 4 + 2] = scl * expf(pv.z - gm);
            sc_s[tid * 4 + 3] = scl * expf(pv.w - gm);
        }
    }
    // ---- convert + swizzled store: elem (c, v) at [c*128 + (v ^ 8*(c&7))] ----
    #pragma unroll
    for (int ph = 0; ph < 8; ph++) {
        const int c = cld + ph * 8;
        uint2 hp, lp;
        bf16_split2(xv[ph].x, xv[ph].y, hp.x, lp.x);
        bf16_split2(xv[ph].z, xv[ph].w, hp.y, lp.y);
        const int off = c * 128 + (vld ^ (8 * (c & 7)));
        *(uint2*)&Xh[off] = hp;
        *(uint2*)&Xl[off] = lp;
    }
    __syncthreads();

    // ---- mma mainloop: warp = 16 vox rows x 64 co ----
    const int wrp  = tid >> 5;
    const int lane = tid & 31;
    const int v0   = wrp * 16;

    float acc[8][4];
    #pragma unroll
    for (int ni = 0; ni < 8; ni++)
        #pragma unroll
        for (int r = 0; r < 4; r++) acc[ni][r] = 0.f;

    const int jA   = lane & 7;
    const int sub  = lane >> 3;                // 0..3
    const int cOfA = (sub >> 1) * 8 + jA;
    const int vOfA = (sub & 1) * 8;
    // B x4: matrix sub -> (ni offset = sub>>1, k chunk = sub&1)
    const int niOfB = sub >> 1;
    const int kSelB = sub & 1;

    #pragma unroll
    for (int ki = 0; ki < 4; ki++) {
        const int k0 = ki * 16;
        uint32_t Ah[4], Al[4];
        {
            const int c = k0 + cOfA;
            const int v = v0 + vOfA;
            const uint32_t off = (uint32_t)(c * 128 + (v ^ (8 * (c & 7)))) * 2u;
            ldmA(Ah, sbase + SM_XH + off);
            ldmA(Al, sbase + SM_XL + off);
        }
        #pragma unroll
        for (int np = 0; np < 4; np++) {       // ni pair {2np, 2np+1}
            const int n = (np * 2 + niOfB) * 8 + jA;
            const int k = k0 + 8 * kSelB;
            const uint32_t off = (uint32_t)(n * 64 + (k ^ (8 * (n & 7)))) * 2u;
            uint32_t Bh[4], Bl[4];
            ldmB4(Bh, sbase + SM_WH + off);
            ldmB4(Bl, sbase + SM_WL + off);
            mma_bf16(acc[np * 2],     Ah, Bh);
            mma_bf16(acc[np * 2],     Al, Bh);
            mma_bf16(acc[np * 2],     Ah, Bl);
            mma_bf16(acc[np * 2 + 1], Ah, Bh + 2);
            mma_bf16(acc[np * 2 + 1], Al, Bh + 2);
            mma_bf16(acc[np * 2 + 1], Ah, Bl + 2);
        }
    }
    __syncthreads();           // done with Xh/Xl/W smem; overlay Ds

    // ---- stage D to smem: Ds[co][vox], row stride 132 floats ----
    float* Ds = (float*)dsm;
    {
        const int g = lane >> 2, t4 = lane & 3;
        const int m = v0 + g;
        #pragma unroll
        for (int ni = 0; ni < 8; ni++) {
            const int n = ni * 8 + t4 * 2;
            Ds[n * 132 + m]           = acc[ni][0];
            Ds[(n + 1) * 132 + m]     = acc[ni][1];
            Ds[n * 132 + m + 8]       = acc[ni][2];
            Ds[(n + 1) * 132 + m + 8] = acc[ni][3];
        }
    }
    __syncthreads();

    // ---- epilogue: warp = 8 co rows, lane covers full 128-vox row (512B stores)
    {
        const int v = lane * 4;
        const float4 sv = *(const float4*)&sc_s[v];
        #pragma unroll
        for (int r = 0; r < 8; r++) {
            const int co = wrp * 8 + r;
            const float bvv = s_bv[co];
            float4 dv = *(const float4*)&Ds[co * 132 + v];
            dv.x = (dv.x + bvv) * sv.x;
            dv.y = (dv.y + bvv) * sv.y;
            dv.z = (dv.z + bvv) * sv.z;
            dv.w = (dv.w + bvv) * sv.w;
            *(float4*)&out[((size_t)(b * CC + co)) * NVOX + n0 + v] = dv;
        }
    }
}

// ---------------- host launcher ----------------
extern "C" void kernel_launch(void* const* d_in, const int* in_sizes, int n_in,
                              void* d_out, int out_size) {
    const float* x     = (const float*)d_in[0];
    const float* mask  = (const float*)d_in[1];
    const float* Wk    = (const float*)d_in[2];
    const float* bk    = (const float*)d_in[3];
    const float* Wv    = (const float*)d_in[4];
    const float* bv    = (const float*)d_in[5];
    const float* Wq    = (const float*)d_in[6];
    const float* bq    = (const float*)d_in[7];
    const float* h_tab = (const float*)d_in[8];
    const float* w_tab = (const float*)d_in[9];
    const float* d_tab = (const float*)d_in[10];
    float* out = (float*)d_out;

    cudaFuncSetAttribute(k_out_mma, cudaFuncAttributeMaxDynamicSharedMemorySize,
                         OUT_SMEM_DYN);

    k_wsplit <<<17, 256>>>(Wv);                     // includes scratch zeroing
    k_reduce <<<dim3(256, BB), 256>>>(x, mask);
    k_prep   <<<BB, 256>>>(Wk, bk, Wq, bq, h_tab, w_tab, d_tab);
    k_logits <<<dim3(NBLK_L, BB), 256>>>(x);
    k_finish <<<BB, NBLK_L>>>();
    k_out_mma<<<dim3(NVOX / TILE_V, BB), 256, OUT_SMEM_DYN>>>(x, bv, out);

    // output tuple tail: mask passthrough
    cudaMemcpyAsync(out + (size_t)BB * CC * NVOX, mask,
                    (size_t)BB * NVOX * sizeof(float),
                    cudaMemcpyDeviceToDevice, 0);
}